// round 1
// baseline (speedup 1.0000x reference)
#include <cuda_runtime.h>
#include <cstdint>

#define BB 128
#define TT 1024
#define HH 256
#define RW 160           // W_hh columns kept in registers per thread
#define SW 96            // W_hh columns kept in shared memory (HH - RW)

// scratch: per-row squared norms of p
__device__ float g_sq[BB * TT];

// ---------------------------------------------------------------------------
// RNN kernel: one block per batch, thread j owns output neuron j.
// h0 MLP computed in the prologue. W_hh row j: first RW entries in registers,
// last SW entries in SMEM laid out [k][j] (conflict-free).
// ---------------------------------------------------------------------------
__global__ void __launch_bounds__(256, 1) rnn_kernel(
    const float* __restrict__ x,   const float* __restrict__ W1,
    const float* __restrict__ b1,  const float* __restrict__ W2,
    const float* __restrict__ b2,  const float* __restrict__ Wih,
    const float* __restrict__ Whh, float* __restrict__ p_out)
{
    extern __shared__ float sm[];
    float* hbuf = sm;            // 2 * 256 (ping-pong h)
    float* hid  = sm + 512;      // 64
    float* Ws   = sm + 576;      // SW * 256

    const int j = threadIdx.x;
    const int b = blockIdx.x;

    // stage SMEM weight chunk: Ws[k][j] = Whh[j][RW+k]
    for (int k = 0; k < SW; ++k)
        Ws[k * HH + j] = Whh[j * HH + RW + k];

    // register weight chunk
    float wr[RW];
#pragma unroll
    for (int k = 0; k < RW; ++k) wr[k] = Whh[j * HH + k];

    const float wi0 = Wih[j * 3 + 0];
    const float wi1 = Wih[j * 3 + 1];
    const float wi2 = Wih[j * 3 + 2];

    // h0 = relu(relu(ones(2) @ W1^T + b1) @ W2^T + b2)  (same for every batch)
    if (j < 64) {
        float s = b1[j] + W1[j * 2 + 0] + W1[j * 2 + 1];
        hid[j] = fmaxf(s, 0.f);
    }
    __syncthreads();
    {
        float acc = b2[j];
#pragma unroll
        for (int k = 0; k < 64; ++k) acc = fmaf(W2[j * 64 + k], hid[k], acc);
        hbuf[j] = fmaxf(acc, 0.f);
    }
    __syncthreads();

    const float* xb = x + (size_t)b * TT * 3;
    float* pb = p_out + (size_t)b * TT * HH;

    int cur = 0;
    for (int t = 0; t < TT; ++t) {
        const float x0 = __ldg(xb + t * 3 + 0);
        const float x1 = __ldg(xb + t * 3 + 1);
        const float x2 = __ldg(xb + t * 3 + 2);
        const float* hc = hbuf + cur * HH;

        float a0 = wi0 * x0;
        float a1 = wi1 * x1;
        float a2 = wi2 * x2;
        float a3 = 0.f;

#pragma unroll
        for (int k = 0; k < RW; k += 4) {
            float4 h4 = *reinterpret_cast<const float4*>(hc + k);
            a0 = fmaf(wr[k + 0], h4.x, a0);
            a1 = fmaf(wr[k + 1], h4.y, a1);
            a2 = fmaf(wr[k + 2], h4.z, a2);
            a3 = fmaf(wr[k + 3], h4.w, a3);
        }
#pragma unroll
        for (int k = 0; k < SW; k += 4) {
            float4 h4 = *reinterpret_cast<const float4*>(hc + RW + k);
            a0 = fmaf(Ws[(k + 0) * HH + j], h4.x, a0);
            a1 = fmaf(Ws[(k + 1) * HH + j], h4.y, a1);
            a2 = fmaf(Ws[(k + 2) * HH + j], h4.z, a2);
            a3 = fmaf(Ws[(k + 3) * HH + j], h4.w, a3);
        }

        const float h = fmaxf((a0 + a1) + (a2 + a3), 0.f);
        hbuf[(cur ^ 1) * HH + j] = h;
        pb[(size_t)t * HH + j] = h;
        __syncthreads();
        cur ^= 1;
    }
}

// ---------------------------------------------------------------------------
// Squared-norm kernel: one warp per row of p
// ---------------------------------------------------------------------------
__global__ void sq_kernel(const float* __restrict__ p)
{
    const int w = threadIdx.x >> 5;
    const int lane = threadIdx.x & 31;
    const int row = blockIdx.x * 8 + w;
    const float* pr = p + (size_t)row * HH;

    float4 v0 = *reinterpret_cast<const float4*>(pr + lane * 4);
    float4 v1 = *reinterpret_cast<const float4*>(pr + 128 + lane * 4);
    float s = v0.x * v0.x + v0.y * v0.y + v0.z * v0.z + v0.w * v0.w
            + v1.x * v1.x + v1.y * v1.y + v1.z * v1.z + v1.w * v1.w;
#pragma unroll
    for (int o = 16; o > 0; o >>= 1) s += __shfl_xor_sync(0xFFFFFFFFu, s, o);
    if (lane == 0) g_sq[row] = s;
}

// ---------------------------------------------------------------------------
// gram/corr kernel: batched SYRK with fused exp epilogue.
// Grid (36, 128): 36 upper-triangular 128x128 tile pairs per batch.
// Stages exp tile through padded SMEM so the mirrored write is coalesced.
// ---------------------------------------------------------------------------
__global__ void __launch_bounds__(256, 2) gram_kernel(
    const float* __restrict__ p, float* __restrict__ corr)
{
    extern __shared__ float sm[];
    float* As = sm;                  // 16 * 132
    float* Bs = sm + 16 * 132;       // 16 * 132
    float* stage = sm;               // 128 * 132 (reused after mainloop)
    __shared__ float sqa[128], sqb[128];

    const int b = blockIdx.y;
    int pair = blockIdx.x;
    int ti = 0;
    while (pair >= 8 - ti) { pair -= (8 - ti); ++ti; }
    const int tj = ti + pair;
    const int tib = ti * 128;
    const int tjb = tj * 128;

    const int tid = threadIdx.x;
    const int tx = tid & 15;
    const int ty = tid >> 4;

    const float* pA = p + ((size_t)b * TT + tib) * HH;
    const float* pB = p + ((size_t)b * TT + tjb) * HH;

    float acc[8][8];
#pragma unroll
    for (int i = 0; i < 8; ++i)
#pragma unroll
        for (int jj = 0; jj < 8; ++jj) acc[i][jj] = 0.f;

    for (int kk = 0; kk < HH; kk += 16) {
        __syncthreads();
#pragma unroll
        for (int v = 0; v < 2; ++v) {
            const int fi = tid + v * 256;      // 0..511
            const int row = fi >> 2;
            const int kc = (fi & 3) * 4;
            float4 a  = *reinterpret_cast<const float4*>(pA + (size_t)row * HH + kk + kc);
            float4 bv = *reinterpret_cast<const float4*>(pB + (size_t)row * HH + kk + kc);
            As[(kc + 0) * 132 + row] = a.x;
            As[(kc + 1) * 132 + row] = a.y;
            As[(kc + 2) * 132 + row] = a.z;
            As[(kc + 3) * 132 + row] = a.w;
            Bs[(kc + 0) * 132 + row] = bv.x;
            Bs[(kc + 1) * 132 + row] = bv.y;
            Bs[(kc + 2) * 132 + row] = bv.z;
            Bs[(kc + 3) * 132 + row] = bv.w;
        }
        __syncthreads();
#pragma unroll
        for (int k = 0; k < 16; ++k) {
            float4 a0 = *reinterpret_cast<float4*>(&As[k * 132 + ty * 8]);
            float4 a1 = *reinterpret_cast<float4*>(&As[k * 132 + ty * 8 + 4]);
            float4 b0 = *reinterpret_cast<float4*>(&Bs[k * 132 + tx * 8]);
            float4 b1 = *reinterpret_cast<float4*>(&Bs[k * 132 + tx * 8 + 4]);
            float av[8] = {a0.x, a0.y, a0.z, a0.w, a1.x, a1.y, a1.z, a1.w};
            float bv[8] = {b0.x, b0.y, b0.z, b0.w, b1.x, b1.y, b1.z, b1.w};
#pragma unroll
            for (int i = 0; i < 8; ++i)
#pragma unroll
                for (int jj = 0; jj < 8; ++jj)
                    acc[i][jj] = fmaf(av[i], bv[jj], acc[i][jj]);
        }
    }

    __syncthreads();
    if (tid < 128) sqa[tid] = g_sq[b * TT + tib + tid];
    else           sqb[tid - 128] = g_sq[b * TT + tjb + (tid - 128)];
    __syncthreads();

#pragma unroll
    for (int i = 0; i < 8; ++i) {
        const float si = sqa[ty * 8 + i];
#pragma unroll
        for (int jj = 0; jj < 8; ++jj) {
            float dp = si + sqb[tx * 8 + jj] - 2.f * acc[i][jj];
            dp = fmaxf(dp, 0.f);
            stage[(ty * 8 + i) * 132 + tx * 8 + jj] = __expf(-dp);
        }
    }
    __syncthreads();

    float* cb = corr + (size_t)b * TT * TT;
#pragma unroll
    for (int m = 0; m < 16; ++m) {
        const int idx = m * 256 + tid;
        const int row = idx >> 5;
        const int c4 = (idx & 31) * 4;
        float4 v = *reinterpret_cast<float4*>(&stage[row * 132 + c4]);
        *reinterpret_cast<float4*>(cb + (size_t)(tib + row) * TT + tjb + c4) = v;
    }
    if (ti != tj) {
        for (int m = 0; m < 64; ++m) {
            const int idx = m * 256 + tid;
            const int c = idx >> 7;
            const int r = idx & 127;
            cb[(size_t)(tjb + c) * TT + tib + r] = stage[r * 132 + c];
        }
    }
}

// ---------------------------------------------------------------------------
extern "C" void kernel_launch(void* const* d_in, const int* in_sizes, int n_in,
                              void* d_out, int out_size)
{
    const float* x   = (const float*)d_in[0];
    const float* W1  = (const float*)d_in[1];
    const float* b1  = (const float*)d_in[2];
    const float* W2  = (const float*)d_in[3];
    const float* b2  = (const float*)d_in[4];
    const float* Wih = (const float*)d_in[5];
    const float* Whh = (const float*)d_in[6];

    float* out  = (float*)d_out;
    float* corr = out;                                 // [B, T, T]
    float* p    = out + (size_t)BB * TT * TT;          // [B, T, H]

    const size_t rnn_smem  = (size_t)(576 + SW * HH) * sizeof(float);   // ~98.3 KB
    const size_t gram_smem = (size_t)(128 * 132) * sizeof(float);       // 67.5 KB
    cudaFuncSetAttribute(rnn_kernel,  cudaFuncAttributeMaxDynamicSharedMemorySize, (int)rnn_smem);
    cudaFuncSetAttribute(gram_kernel, cudaFuncAttributeMaxDynamicSharedMemorySize, (int)gram_smem);

    rnn_kernel<<<BB, 256, rnn_smem>>>(x, W1, b1, W2, b2, Wih, Whh, p);
    sq_kernel<<<(BB * TT) / 8, 256>>>(p);
    gram_kernel<<<dim3(36, BB), 256, gram_smem>>>(p, corr);
}

// round 2
// speedup vs baseline: 1.0701x; 1.0701x over previous
#include <cuda_runtime.h>
#include <cstdint>

#define BB 128
#define TT 1024
#define HH 256
#define RW 200           // W_hh columns kept in registers per thread (100 f32x2 pairs)
#define SW 56            // W_hh columns kept in shared memory (14 groups of 4)

typedef unsigned long long ull;

// scratch: per-row squared norms of p
__device__ float g_sq[BB * TT];

// ---------------- packed fp32x2 helpers (Blackwell FFMA2) ----------------
__device__ __forceinline__ ull pack2(float lo, float hi) {
    ull r;
    asm("mov.b64 %0, {%1, %2};" : "=l"(r) : "r"(__float_as_uint(lo)), "r"(__float_as_uint(hi)));
    return r;
}
__device__ __forceinline__ void ffma2(ull& acc, ull a, ull b) {
    asm("fma.rn.f32x2 %0, %1, %2, %3;" : "=l"(acc) : "l"(a), "l"(b), "l"(acc));
}
__device__ __forceinline__ float2 unpack2(ull v) {
    unsigned lo, hi;
    asm("mov.b64 {%0, %1}, %2;" : "=r"(lo), "=r"(hi) : "l"(v));
    return make_float2(__uint_as_float(lo), __uint_as_float(hi));
}

// ---------------------------------------------------------------------------
// RNN kernel: one block per batch, thread j owns output neuron j.
// W_hh row j: first RW entries pre-packed in registers, last SW entries in
// SMEM pre-packed as ulonglong2 (f32x2 pairs), loaded via LDS.128.
// ---------------------------------------------------------------------------
__global__ void __launch_bounds__(256, 1) rnn_kernel(
    const float* __restrict__ x,   const float* __restrict__ W1,
    const float* __restrict__ b1,  const float* __restrict__ W2,
    const float* __restrict__ b2,  const float* __restrict__ Wih,
    const float* __restrict__ Whh, float* __restrict__ p_out)
{
    extern __shared__ float sm[];
    float* hbuf = sm;                                  // 2 * 256 (ping-pong h)
    float* hid  = sm + 512;                            // 64
    ulonglong2* Ws = reinterpret_cast<ulonglong2*>(sm + 576);  // (SW/4) * 256 entries

    const int j = threadIdx.x;
    const int b = blockIdx.x;

    // stage SMEM weight chunk, pre-packed: Ws[g*256+j] = pairs of Whh[j][RW+4g .. +3]
    for (int g = 0; g < SW / 4; ++g) {
        float4 w = *reinterpret_cast<const float4*>(Whh + (size_t)j * HH + RW + 4 * g);
        Ws[g * HH + j] = make_ulonglong2(pack2(w.x, w.y), pack2(w.z, w.w));
    }

    // register weight chunk, packed as pairs
    ull wr2[RW / 2];
#pragma unroll
    for (int q = 0; q < RW / 2; ++q) {
        float2 w = *reinterpret_cast<const float2*>(Whh + (size_t)j * HH + 2 * q);
        wr2[q] = pack2(w.x, w.y);
    }

    const float wi0 = Wih[j * 3 + 0];
    const float wi1 = Wih[j * 3 + 1];
    const float wi2 = Wih[j * 3 + 2];

    // h0 = relu(relu(ones(2) @ W1^T + b1) @ W2^T + b2)  (same for every batch)
    if (j < 64) {
        float s = b1[j] + W1[j * 2 + 0] + W1[j * 2 + 1];
        hid[j] = fmaxf(s, 0.f);
    }
    __syncthreads();
    {
        float acc = b2[j];
#pragma unroll
        for (int k = 0; k < 64; ++k) acc = fmaf(W2[j * 64 + k], hid[k], acc);
        hbuf[j] = fmaxf(acc, 0.f);
    }
    __syncthreads();

    const float* xb = x + (size_t)b * TT * 3;
    float* pb = p_out + (size_t)b * TT * HH;

    int cur = 0;
    for (int t = 0; t < TT; ++t) {
        const float x0 = __ldg(xb + t * 3 + 0);
        const float x1 = __ldg(xb + t * 3 + 1);
        const float x2 = __ldg(xb + t * 3 + 2);
        const float* hc = hbuf + cur * HH;

        ull a0 = pack2(wi0 * x0, wi1 * x1);
        ull a1 = pack2(wi2 * x2, 0.f);
        ull a2 = pack2(0.f, 0.f);
        ull a3 = a2;

        // register part: k in [0, RW), 4 floats (2 pairs) per iteration
#pragma unroll
        for (int q = 0; q < RW / 4; ++q) {          // 50 iterations
            ulonglong2 h2 = *reinterpret_cast<const ulonglong2*>(hc + 4 * q);
            if (q & 1) { ffma2(a2, wr2[2 * q], h2.x); ffma2(a3, wr2[2 * q + 1], h2.y); }
            else       { ffma2(a0, wr2[2 * q], h2.x); ffma2(a1, wr2[2 * q + 1], h2.y); }
        }
        // SMEM part: k in [RW, 256)
#pragma unroll
        for (int g = 0; g < SW / 4; ++g) {          // 14 iterations
            ulonglong2 w2 = Ws[g * HH + j];
            ulonglong2 h2 = *reinterpret_cast<const ulonglong2*>(hc + RW + 4 * g);
            if (g & 1) { ffma2(a2, w2.x, h2.x); ffma2(a3, w2.y, h2.y); }
            else       { ffma2(a0, w2.x, h2.x); ffma2(a1, w2.y, h2.y); }
        }

        float2 f0 = unpack2(a0), f1 = unpack2(a1), f2 = unpack2(a2), f3 = unpack2(a3);
        const float h = fmaxf(((f0.x + f0.y) + (f1.x + f1.y)) +
                              ((f2.x + f2.y) + (f3.x + f3.y)), 0.f);
        hbuf[(cur ^ 1) * HH + j] = h;
        pb[(size_t)t * HH + j] = h;
        __syncthreads();
        cur ^= 1;
    }
}

// ---------------------------------------------------------------------------
// Squared-norm kernel: one warp per row of p
// ---------------------------------------------------------------------------
__global__ void sq_kernel(const float* __restrict__ p)
{
    const int w = threadIdx.x >> 5;
    const int lane = threadIdx.x & 31;
    const int row = blockIdx.x * 8 + w;
    const float* pr = p + (size_t)row * HH;

    float4 v0 = *reinterpret_cast<const float4*>(pr + lane * 4);
    float4 v1 = *reinterpret_cast<const float4*>(pr + 128 + lane * 4);
    float s = v0.x * v0.x + v0.y * v0.y + v0.z * v0.z + v0.w * v0.w
            + v1.x * v1.x + v1.y * v1.y + v1.z * v1.z + v1.w * v1.w;
#pragma unroll
    for (int o = 16; o > 0; o >>= 1) s += __shfl_xor_sync(0xFFFFFFFFu, s, o);
    if (lane == 0) g_sq[row] = s;
}

// ---------------------------------------------------------------------------
// gram/corr kernel: batched SYRK with fused exp epilogue, FFMA2 inner loop.
// Grid (36, 128): 36 upper-triangular 128x128 tile pairs per batch.
// ---------------------------------------------------------------------------
__global__ void __launch_bounds__(256, 2) gram_kernel(
    const float* __restrict__ p, float* __restrict__ corr)
{
    extern __shared__ float sm[];
    float* As = sm;                  // 16 * 132
    float* Bs = sm + 16 * 132;       // 16 * 132
    float* stage = sm;               // 128 * 132 (reused after mainloop)
    __shared__ float sqa[128], sqb[128];

    const int b = blockIdx.y;
    int pair = blockIdx.x;
    int ti = 0;
    while (pair >= 8 - ti) { pair -= (8 - ti); ++ti; }
    const int tj = ti + pair;
    const int tib = ti * 128;
    const int tjb = tj * 128;

    const int tid = threadIdx.x;
    const int tx = tid & 15;
    const int ty = tid >> 4;

    const float* pA = p + ((size_t)b * TT + tib) * HH;
    const float* pB = p + ((size_t)b * TT + tjb) * HH;

    ull acc2[8][4];
#pragma unroll
    for (int i = 0; i < 8; ++i)
#pragma unroll
        for (int jj = 0; jj < 4; ++jj) acc2[i][jj] = 0ULL;

    for (int kk = 0; kk < HH; kk += 16) {
        __syncthreads();
#pragma unroll
        for (int v = 0; v < 2; ++v) {
            const int fi = tid + v * 256;      // 0..511
            const int row = fi >> 2;
            const int kc = (fi & 3) * 4;
            float4 a  = *reinterpret_cast<const float4*>(pA + (size_t)row * HH + kk + kc);
            float4 bv = *reinterpret_cast<const float4*>(pB + (size_t)row * HH + kk + kc);
            As[(kc + 0) * 132 + row] = a.x;
            As[(kc + 1) * 132 + row] = a.y;
            As[(kc + 2) * 132 + row] = a.z;
            As[(kc + 3) * 132 + row] = a.w;
            Bs[(kc + 0) * 132 + row] = bv.x;
            Bs[(kc + 1) * 132 + row] = bv.y;
            Bs[(kc + 2) * 132 + row] = bv.z;
            Bs[(kc + 3) * 132 + row] = bv.w;
        }
        __syncthreads();
#pragma unroll
        for (int k = 0; k < 16; ++k) {
            float4 a0 = *reinterpret_cast<float4*>(&As[k * 132 + ty * 8]);
            float4 a1 = *reinterpret_cast<float4*>(&As[k * 132 + ty * 8 + 4]);
            ulonglong2 b0 = *reinterpret_cast<ulonglong2*>(&Bs[k * 132 + tx * 8]);
            ulonglong2 b1 = *reinterpret_cast<ulonglong2*>(&Bs[k * 132 + tx * 8 + 4]);
            ull ad[8];
            ad[0] = pack2(a0.x, a0.x); ad[1] = pack2(a0.y, a0.y);
            ad[2] = pack2(a0.z, a0.z); ad[3] = pack2(a0.w, a0.w);
            ad[4] = pack2(a1.x, a1.x); ad[5] = pack2(a1.y, a1.y);
            ad[6] = pack2(a1.z, a1.z); ad[7] = pack2(a1.w, a1.w);
            ull bv2[4] = {b0.x, b0.y, b1.x, b1.y};
#pragma unroll
            for (int i = 0; i < 8; ++i)
#pragma unroll
                for (int jj = 0; jj < 4; ++jj)
                    ffma2(acc2[i][jj], ad[i], bv2[jj]);
        }
    }

    __syncthreads();
    if (tid < 128) sqa[tid] = g_sq[b * TT + tib + tid];
    else           sqb[tid - 128] = g_sq[b * TT + tjb + (tid - 128)];
    __syncthreads();

#pragma unroll
    for (int i = 0; i < 8; ++i) {
        const float si = sqa[ty * 8 + i];
#pragma unroll
        for (int jj = 0; jj < 4; ++jj) {
            float2 c = unpack2(acc2[i][jj]);
            float dp0 = fmaxf(si + sqb[tx * 8 + 2 * jj]     - 2.f * c.x, 0.f);
            float dp1 = fmaxf(si + sqb[tx * 8 + 2 * jj + 1] - 2.f * c.y, 0.f);
            stage[(ty * 8 + i) * 132 + tx * 8 + 2 * jj]     = __expf(-dp0);
            stage[(ty * 8 + i) * 132 + tx * 8 + 2 * jj + 1] = __expf(-dp1);
        }
    }
    __syncthreads();

    float* cb = corr + (size_t)b * TT * TT;
#pragma unroll
    for (int m = 0; m < 16; ++m) {
        const int idx = m * 256 + tid;
        const int row = idx >> 5;
        const int c4 = (idx & 31) * 4;
        float4 v = *reinterpret_cast<float4*>(&stage[row * 132 + c4]);
        *reinterpret_cast<float4*>(cb + (size_t)(tib + row) * TT + tjb + c4) = v;
    }
    if (ti != tj) {
        for (int m = 0; m < 64; ++m) {
            const int idx = m * 256 + tid;
            const int c = idx >> 7;
            const int r = idx & 127;
            cb[(size_t)(tjb + c) * TT + tib + r] = stage[r * 132 + c];
        }
    }
}

// ---------------------------------------------------------------------------
extern "C" void kernel_launch(void* const* d_in, const int* in_sizes, int n_in,
                              void* d_out, int out_size)
{
    const float* x   = (const float*)d_in[0];
    const float* W1  = (const float*)d_in[1];
    const float* b1  = (const float*)d_in[2];
    const float* W2  = (const float*)d_in[3];
    const float* b2  = (const float*)d_in[4];
    const float* Wih = (const float*)d_in[5];
    const float* Whh = (const float*)d_in[6];

    float* out  = (float*)d_out;
    float* corr = out;                                 // [B, T, T]
    float* p    = out + (size_t)BB * TT * TT;          // [B, T, H]

    const size_t rnn_smem  = 576 * sizeof(float) + (size_t)(SW / 4) * HH * sizeof(ulonglong2);
    const size_t gram_smem = (size_t)(128 * 132) * sizeof(float);       // 67.5 KB
    cudaFuncSetAttribute(rnn_kernel,  cudaFuncAttributeMaxDynamicSharedMemorySize, (int)rnn_smem);
    cudaFuncSetAttribute(gram_kernel, cudaFuncAttributeMaxDynamicSharedMemorySize, (int)gram_smem);

    rnn_kernel<<<BB, 256, rnn_smem>>>(x, W1, b1, W2, b2, Wih, Whh, p);
    sq_kernel<<<(BB * TT) / 8, 256>>>(p);
    gram_kernel<<<dim3(36, BB), 256, gram_smem>>>(p, corr);
}